// round 1
// baseline (speedup 1.0000x reference)
#include <cuda_runtime.h>
#include <cuda_bf16.h>

#define N_USERS  100000
#define N_ITEMS  50000
#define N_TOPICS 1000
#define N_NODES  (N_USERS + N_ITEMS + N_TOPICS)   // 151000
#define DIM      64
#define NNZ      4000000
#define BATCH    16384

#define VEC_PER_ROW   (DIM / 4)                   // 16 float4 per node row
#define TOTAL_VEC     (N_NODES * VEC_PER_ROW)     // 2,416,000 float4

// Scratch: ping-pong embedding buffers + accumulator (38.7 MB each).
__device__ float4 g_A[TOTAL_VEC];
__device__ float4 g_B[TOTAL_VEC];
__device__ float4 g_acc[TOTAL_VEC];

// ---------------------------------------------------------------------------
// init: A = all_emb (concat of user/item/topic), acc = all_emb, B = 0
// ---------------------------------------------------------------------------
__global__ void init_kernel(const float4* __restrict__ user_w,
                            const float4* __restrict__ item_w,
                            const float4* __restrict__ topic_w) {
    int i = blockIdx.x * blockDim.x + threadIdx.x;
    if (i >= TOTAL_VEC) return;
    int node  = i / VEC_PER_ROW;
    int chunk = i % VEC_PER_ROW;
    float4 v;
    if (node < N_USERS) {
        v = user_w[node * VEC_PER_ROW + chunk];
    } else if (node < N_USERS + N_ITEMS) {
        v = item_w[(node - N_USERS) * VEC_PER_ROW + chunk];
    } else {
        v = topic_w[(node - N_USERS - N_ITEMS) * VEC_PER_ROW + chunk];
    }
    g_A[i]   = v;
    g_acc[i] = v;
    g_B[i]   = make_float4(0.f, 0.f, 0.f, 0.f);
}

// ---------------------------------------------------------------------------
// spmm: y[row[e]] += vals[e] * x[col[e]]    (16 lanes per edge, float4 each)
// ---------------------------------------------------------------------------
__global__ void spmm_kernel(const float4* __restrict__ x,
                            float4* __restrict__ y,
                            const float* __restrict__ vals,
                            const int* __restrict__ row,
                            const int* __restrict__ col) {
    long long g = (long long)blockIdx.x * blockDim.x + threadIdx.x;
    int edge = (int)(g >> 4);
    int lane = (int)(g & 15);
    if (edge >= NNZ) return;

    float v = __ldg(vals + edge);
    int   r = __ldg(row  + edge);
    int   c = __ldg(col  + edge);

    float4 xv = x[c * VEC_PER_ROW + lane];
    float4 m  = make_float4(v * xv.x, v * xv.y, v * xv.z, v * xv.w);
    atomicAdd(&y[r * VEC_PER_ROW + lane], m);   // native 128-bit RED on sm_90+
}

// ---------------------------------------------------------------------------
// fused: acc += src; dst_to_zero = 0   (prepares next layer's output buffer)
// ---------------------------------------------------------------------------
__global__ void acc_zero_kernel(const float4* __restrict__ src,
                                float4* __restrict__ to_zero) {
    int i = blockIdx.x * blockDim.x + threadIdx.x;
    if (i >= TOTAL_VEC) return;
    float4 a = g_acc[i];
    float4 s = src[i];
    g_acc[i] = make_float4(a.x + s.x, a.y + s.y, a.z + s.z, a.w + s.w);
    to_zero[i] = make_float4(0.f, 0.f, 0.f, 0.f);
}

// ---------------------------------------------------------------------------
// gather: out[b] = dot(acc[u]+last[u], acc[i]+last[i]) / 16
//   (acc holds emb0+emb1+emb2; last holds emb3; /4 per operand -> /16 on dot)
// ---------------------------------------------------------------------------
__global__ void gather_kernel(const float2* __restrict__ acc,
                              const float2* __restrict__ last,
                              const int* __restrict__ users,
                              const int* __restrict__ items,
                              float* __restrict__ out) {
    int warp = (blockIdx.x * blockDim.x + threadIdx.x) >> 5;
    int lane = threadIdx.x & 31;
    if (warp >= BATCH) return;

    int u  = __ldg(users + warp);
    int it = N_USERS + __ldg(items + warp);

    // 32 lanes x float2 = 64 floats
    float2 au = acc [u  * 32 + lane];
    float2 lu = last[u  * 32 + lane];
    float2 ai = acc [it * 32 + lane];
    float2 li = last[it * 32 + lane];

    float ux = au.x + lu.x, uy = au.y + lu.y;
    float ix = ai.x + li.x, iy = ai.y + li.y;
    float s = ux * ix + uy * iy;

    #pragma unroll
    for (int o = 16; o > 0; o >>= 1)
        s += __shfl_xor_sync(0xffffffffu, s, o);

    if (lane == 0) out[warp] = s * (1.0f / 16.0f);
}

// ---------------------------------------------------------------------------
extern "C" void kernel_launch(void* const* d_in, const int* in_sizes, int n_in,
                              void* d_out, int out_size) {
    const float4* user_w  = (const float4*)d_in[0];
    const float4* item_w  = (const float4*)d_in[1];
    const float4* topic_w = (const float4*)d_in[2];
    const float*  vals    = (const float*)d_in[3];
    const int*    row     = (const int*)d_in[4];
    const int*    col     = (const int*)d_in[5];
    const int*    users   = (const int*)d_in[6];
    const int*    items   = (const int*)d_in[7];
    float*        out     = (float*)d_out;

    float4 *A, *B, *ACC;
    cudaGetSymbolAddress((void**)&A,   g_A);
    cudaGetSymbolAddress((void**)&B,   g_B);
    cudaGetSymbolAddress((void**)&ACC, g_acc);

    const int ethreads = 256;
    const int eblocks  = (TOTAL_VEC + ethreads - 1) / ethreads;

    const int sthreads = 256;
    const long long slanes = (long long)NNZ * 16;
    const int sblocks = (int)((slanes + sthreads - 1) / sthreads);

    // init: A = emb, acc = emb, B = 0
    init_kernel<<<eblocks, ethreads>>>(user_w, item_w, topic_w);
    // layer 1: A -> B
    spmm_kernel<<<sblocks, sthreads>>>(A, B, vals, row, col);
    // acc += B; zero A
    acc_zero_kernel<<<eblocks, ethreads>>>(B, A);
    // layer 2: B -> A
    spmm_kernel<<<sblocks, sthreads>>>(B, A, vals, row, col);
    // acc += A; zero B
    acc_zero_kernel<<<eblocks, ethreads>>>(A, B);
    // layer 3: A -> B  (result stays in B; folded into gather)
    spmm_kernel<<<sblocks, sthreads>>>(A, B, vals, row, col);
    // gather dots
    const int gthreads = 256;
    const int gblocks  = (BATCH * 32 + gthreads - 1) / gthreads;
    gather_kernel<<<gblocks, gthreads>>>((const float2*)ACC, (const float2*)B,
                                         users, items, out);
}

// round 2
// speedup vs baseline: 1.7147x; 1.7147x over previous
#include <cuda_runtime.h>
#include <cuda_bf16.h>

#define N_USERS  100000
#define N_ITEMS  50000
#define N_TOPICS 1000
#define N_NODES  (N_USERS + N_ITEMS + N_TOPICS)   // 151000
#define DIM      64
#define NNZ      4000000
#define BATCH    16384

#define VEC_PER_ROW   (DIM / 4)                   // 16 float4 per row
#define F2_PER_ROW    (DIM / 2)                   // 32 float2 per row
#define TOTAL_VEC     (N_NODES * VEC_PER_ROW)
#define SCAN_CHUNK    1024
#define SCAN_NB       ((N_NODES + SCAN_CHUNK - 1) / SCAN_CHUNK)   // 148

// Embedding ping-pong + accumulator (38.7 MB each)
__device__ float4 g_A[TOTAL_VEC];
__device__ float4 g_B[TOTAL_VEC];
__device__ float4 g_acc[TOTAL_VEC];
// CSR scratch
__device__ int    g_cnt[N_NODES];
__device__ int    g_row_ptr[N_NODES + 1];
__device__ int    g_row_off[N_NODES];
__device__ int    g_part[SCAN_NB];
__device__ int    g_part_scan[SCAN_NB];
__device__ int    g_scol[NNZ];
__device__ float  g_sval[NNZ];

// ---------------------------------------------------------------------------
// init: A = all_emb, acc = all_emb, cnt = 0
// ---------------------------------------------------------------------------
__global__ void init_kernel(const float4* __restrict__ user_w,
                            const float4* __restrict__ item_w,
                            const float4* __restrict__ topic_w) {
    int i = blockIdx.x * blockDim.x + threadIdx.x;
    if (i < N_NODES) g_cnt[i] = 0;
    if (i >= TOTAL_VEC) return;
    int node  = i / VEC_PER_ROW;
    int chunk = i % VEC_PER_ROW;
    float4 v;
    if (node < N_USERS)                 v = user_w[node * VEC_PER_ROW + chunk];
    else if (node < N_USERS + N_ITEMS)  v = item_w[(node - N_USERS) * VEC_PER_ROW + chunk];
    else                                v = topic_w[(node - N_USERS - N_ITEMS) * VEC_PER_ROW + chunk];
    g_A[i]   = v;
    g_acc[i] = v;
}

// ---------------------------------------------------------------------------
// CSR build: histogram -> scan -> scatter
// ---------------------------------------------------------------------------
__global__ void hist_kernel(const int* __restrict__ row) {
    int e = blockIdx.x * blockDim.x + threadIdx.x;
    if (e < NNZ) atomicAdd(&g_cnt[row[e]], 1);
}

__global__ void scan_partial_kernel() {
    int b = blockIdx.x, t = threadIdx.x;
    int base = b * SCAN_CHUNK + t * 4;
    int s = 0;
    #pragma unroll
    for (int k = 0; k < 4; k++)
        if (base + k < N_NODES) s += g_cnt[base + k];
    __shared__ int sh[256];
    sh[t] = s; __syncthreads();
    for (int o = 128; o > 0; o >>= 1) {
        if (t < o) sh[t] += sh[t + o];
        __syncthreads();
    }
    if (t == 0) g_part[b] = sh[0];
}

__global__ void scan_top_kernel() {
    __shared__ int sh[256];
    int t = threadIdx.x;
    sh[t] = (t < SCAN_NB) ? g_part[t] : 0;
    __syncthreads();
    for (int o = 1; o < 256; o <<= 1) {
        int x = (t >= o) ? sh[t - o] : 0;
        __syncthreads();
        sh[t] += x;
        __syncthreads();
    }
    if (t < SCAN_NB) g_part_scan[t] = (t > 0) ? sh[t - 1] : 0;
    if (t == 0) g_row_ptr[N_NODES] = NNZ;
}

__global__ void scan_final_kernel() {
    int b = blockIdx.x, t = threadIdx.x;
    int base = b * SCAN_CHUNK + t * 4;
    int v[4];
    #pragma unroll
    for (int k = 0; k < 4; k++)
        v[k] = (base + k < N_NODES) ? g_cnt[base + k] : 0;
    int tsum = v[0] + v[1] + v[2] + v[3];
    __shared__ int sh[256];
    sh[t] = tsum; __syncthreads();
    for (int o = 1; o < 256; o <<= 1) {
        int x = (t >= o) ? sh[t - o] : 0;
        __syncthreads();
        sh[t] += x;
        __syncthreads();
    }
    int run = ((t > 0) ? sh[t - 1] : 0) + g_part_scan[b];
    #pragma unroll
    for (int k = 0; k < 4; k++) {
        if (base + k < N_NODES) {
            g_row_ptr[base + k] = run;
            g_row_off[base + k] = run;
        }
        run += v[k];
    }
}

__global__ void scatter_kernel(const int* __restrict__ row,
                               const int* __restrict__ col,
                               const float* __restrict__ vals) {
    int e = blockIdx.x * blockDim.x + threadIdx.x;
    if (e >= NNZ) return;
    int r = row[e];
    int p = atomicAdd(&g_row_off[r], 1);
    g_scol[p] = col[e];
    g_sval[p] = vals[e];
}

// ---------------------------------------------------------------------------
// CSR SpMM: one warp per row, register accumulation, fused acc += y.
// Each lane owns 2 of the 64 columns (float2). Inner loop unrolled x4 with
// independent accumulators to keep 4 random 256B gathers in flight per warp.
// ---------------------------------------------------------------------------
__global__ void spmm_csr_kernel(const float2* __restrict__ xin,
                                float2* __restrict__ yout,
                                int write_y) {
    int w    = (blockIdx.x * blockDim.x + threadIdx.x) >> 5;
    int lane = threadIdx.x & 31;
    if (w >= N_NODES) return;

    int beg = g_row_ptr[w];
    int end = g_row_ptr[w + 1];

    float2 a0 = {0.f, 0.f}, a1 = {0.f, 0.f}, a2 = {0.f, 0.f}, a3 = {0.f, 0.f};

    for (int e0 = beg; e0 < end; e0 += 32) {
        int   idx = e0 + lane;
        int   c   = (idx < end) ? g_scol[idx] : 0;
        float v   = (idx < end) ? g_sval[idx] : 0.f;
        int   n   = min(32, end - e0);
        int   j   = 0;
        for (; j + 4 <= n; j += 4) {
            int   c0 = __shfl_sync(0xffffffffu, c, j + 0);
            int   c1 = __shfl_sync(0xffffffffu, c, j + 1);
            int   c2 = __shfl_sync(0xffffffffu, c, j + 2);
            int   c3 = __shfl_sync(0xffffffffu, c, j + 3);
            float v0 = __shfl_sync(0xffffffffu, v, j + 0);
            float v1 = __shfl_sync(0xffffffffu, v, j + 1);
            float v2 = __shfl_sync(0xffffffffu, v, j + 2);
            float v3 = __shfl_sync(0xffffffffu, v, j + 3);
            float2 x0 = xin[c0 * F2_PER_ROW + lane];
            float2 x1 = xin[c1 * F2_PER_ROW + lane];
            float2 x2 = xin[c2 * F2_PER_ROW + lane];
            float2 x3 = xin[c3 * F2_PER_ROW + lane];
            a0.x += v0 * x0.x; a0.y += v0 * x0.y;
            a1.x += v1 * x1.x; a1.y += v1 * x1.y;
            a2.x += v2 * x2.x; a2.y += v2 * x2.y;
            a3.x += v3 * x3.x; a3.y += v3 * x3.y;
        }
        for (; j < n; j++) {
            int   cj = __shfl_sync(0xffffffffu, c, j);
            float vj = __shfl_sync(0xffffffffu, v, j);
            float2 xv = xin[cj * F2_PER_ROW + lane];
            a0.x += vj * xv.x; a0.y += vj * xv.y;
        }
    }

    float2 s = { a0.x + a1.x + a2.x + a3.x,
                 a0.y + a1.y + a2.y + a3.y };
    int off = w * F2_PER_ROW + lane;
    if (write_y) yout[off] = s;
    float2* accb = (float2*)g_acc;
    float2 ac = accb[off];
    ac.x += s.x; ac.y += s.y;
    accb[off] = ac;
}

// ---------------------------------------------------------------------------
// gather: out[b] = dot(acc[u], acc[i]) / 16
// ---------------------------------------------------------------------------
__global__ void gather_kernel(const int* __restrict__ users,
                              const int* __restrict__ items,
                              float* __restrict__ out) {
    int warp = (blockIdx.x * blockDim.x + threadIdx.x) >> 5;
    int lane = threadIdx.x & 31;
    if (warp >= BATCH) return;

    int u  = __ldg(users + warp);
    int it = N_USERS + __ldg(items + warp);

    const float2* acc = (const float2*)g_acc;
    float2 au = acc[u  * F2_PER_ROW + lane];
    float2 ai = acc[it * F2_PER_ROW + lane];
    float s = au.x * ai.x + au.y * ai.y;

    #pragma unroll
    for (int o = 16; o > 0; o >>= 1)
        s += __shfl_xor_sync(0xffffffffu, s, o);

    if (lane == 0) out[warp] = s * (1.0f / 16.0f);
}

// ---------------------------------------------------------------------------
extern "C" void kernel_launch(void* const* d_in, const int* in_sizes, int n_in,
                              void* d_out, int out_size) {
    const float4* user_w  = (const float4*)d_in[0];
    const float4* item_w  = (const float4*)d_in[1];
    const float4* topic_w = (const float4*)d_in[2];
    const float*  vals    = (const float*)d_in[3];
    const int*    row     = (const int*)d_in[4];
    const int*    col     = (const int*)d_in[5];
    const int*    users   = (const int*)d_in[6];
    const int*    items   = (const int*)d_in[7];
    float*        out     = (float*)d_out;

    float4 *A, *B;
    cudaGetSymbolAddress((void**)&A, g_A);
    cudaGetSymbolAddress((void**)&B, g_B);

    const int T = 256;
    const int eblocks = (TOTAL_VEC + T - 1) / T;
    const int nblocks = (NNZ + T - 1) / T;
    const int wblocks = (N_NODES * 32 + T - 1) / T;

    // init: A = emb, acc = emb, cnt = 0
    init_kernel<<<eblocks, T>>>(user_w, item_w, topic_w);
    // CSR build
    hist_kernel<<<nblocks, T>>>(row);
    scan_partial_kernel<<<SCAN_NB, 256>>>();
    scan_top_kernel<<<1, 256>>>();
    scan_final_kernel<<<SCAN_NB, 256>>>();
    scatter_kernel<<<nblocks, T>>>(row, col, vals);
    // 3 propagation layers (acc += fused into epilogue)
    spmm_csr_kernel<<<wblocks, T>>>((const float2*)A, (float2*)B, 1);
    spmm_csr_kernel<<<wblocks, T>>>((const float2*)B, (float2*)A, 1);
    spmm_csr_kernel<<<wblocks, T>>>((const float2*)A, (float2*)B, 0);
    // batched dots
    const int gblocks = (BATCH * 32 + T - 1) / T;
    gather_kernel<<<gblocks, T>>>(users, items, out);
}